// round 8
// baseline (speedup 1.0000x reference)
#include <cuda_runtime.h>
#include <cuda_bf16.h>
#include <cstdint>

#define DM   768
#define NH   12
#define DH   64
#define BB   2
#define TT   4096
#define BH   (BB*NH)
#define MTOT (BB*TT)        // 8192

// ---------------- scratch (__device__ globals; no cudaMalloc allowed) ------
__device__ float g_Q[(size_t)BH*TT*DH];
__device__ float g_K[(size_t)BH*TT*DH];
__device__ float g_V[(size_t)BH*TT*DH];
__device__ float g_att[(size_t)BB*TT*DM];

__device__ __align__(256) __nv_bfloat16 g_xh[(size_t)MTOT*DM];
__device__ __align__(256) __nv_bfloat16 g_xl[(size_t)MTOT*DM];
__device__ __align__(256) __nv_bfloat16 g_wqh[(size_t)3*DM*DM];
__device__ __align__(256) __nv_bfloat16 g_wql[(size_t)3*DM*DM];
__device__ __align__(256) __nv_bfloat16 g_woh[(size_t)DM*DM];
__device__ __align__(256) __nv_bfloat16 g_wol[(size_t)DM*DM];
__device__ __align__(256) __nv_bfloat16 g_ath[(size_t)MTOT*DM];
__device__ __align__(256) __nv_bfloat16 g_atl[(size_t)MTOT*DM];

// ---------------- PTX helpers (sm_80-era: legal on plain sm_103) -----------
__device__ __forceinline__ uint32_t smem_u32(const void* p) {
    uint32_t a;
    asm("{ .reg .u64 t; cvta.to.shared.u64 t, %1; cvt.u32.u64 %0, t; }"
        : "=r"(a) : "l"(p));
    return a;
}
__device__ __forceinline__ void ldmx4(uint32_t* r, uint32_t addr) {
    asm volatile("ldmatrix.sync.aligned.m8n8.x4.shared.b16 {%0,%1,%2,%3}, [%4];"
                 : "=r"(r[0]), "=r"(r[1]), "=r"(r[2]), "=r"(r[3]) : "r"(addr));
}
__device__ __forceinline__ void mma16816(float* c, const uint32_t* a,
                                         const uint32_t* b) {
    asm volatile(
        "mma.sync.aligned.m16n8k16.row.col.f32.bf16.bf16.f32 "
        "{%0,%1,%2,%3}, {%4,%5,%6,%7}, {%8,%9}, {%0,%1,%2,%3};"
        : "+f"(c[0]), "+f"(c[1]), "+f"(c[2]), "+f"(c[3])
        : "r"(a[0]), "r"(a[1]), "r"(a[2]), "r"(a[3]), "r"(b[0]), "r"(b[1]));
}
#define CP16(saddr, gptr) \
    asm volatile("cp.async.cg.shared.global [%0], [%1], 16;" \
                 :: "r"(saddr), "l"(gptr))
#define CPCOMMIT() asm volatile("cp.async.commit_group;" ::: "memory")
#define CPWAIT(n)  asm volatile("cp.async.wait_group %0;" :: "n"(n) : "memory")

// ---------------- fp32 -> bf16 hi/lo split ----------------------------------
__global__ __launch_bounds__(256) void split_kernel(const float* __restrict__ in,
                                                    __nv_bfloat162* __restrict__ hi,
                                                    __nv_bfloat162* __restrict__ lo,
                                                    int n2) {
    int i = blockIdx.x * 256 + threadIdx.x;
    if (i < n2) {
        float2 v = ((const float2*)in)[i];
        __nv_bfloat16 hx = __float2bfloat16(v.x);
        __nv_bfloat16 hy = __float2bfloat16(v.y);
        float rx = v.x - __bfloat162float(hx);
        float ry = v.y - __bfloat162float(hy);
        hi[i] = __halves2bfloat162(hx, hy);
        lo[i] = __halves2bfloat162(__float2bfloat16(rx), __float2bfloat16(ry));
    }
}

// ---------------- HMMA GEMM: C = A @ B^T (+bias) ----------------------------
// A [M x 768] bf16 hi/lo row-major, B [N x 768] bf16 hi/lo row-major.
// CTA 128x128, 8 warps (warp tile 64x32), k-tile 32, double-buffered cp.async.
// 3-term split: C = Ah*Bh + Ah*Bl + Al*Bh.
// MODE 0: qkv scatter into g_Q/g_K/g_V (Q scaled 0.125). MODE 1: dst[m*768+n].
#define KT       32
#define SSTRIDE  40                         // bf16 per smem row (pad: 80 B)
#define TILE_B   (128 * SSTRIDE * 2)        // 10240
#define STAGE_B  (4 * TILE_B)               // 40960
#define GEMM_SMEM (2 * STAGE_B)             // 81920

template <int MODE>
__global__ __launch_bounds__(256) void gemm_mma(const __nv_bfloat16* __restrict__ Ah,
                                                const __nv_bfloat16* __restrict__ Al,
                                                const __nv_bfloat16* __restrict__ Bh,
                                                const __nv_bfloat16* __restrict__ Bl,
                                                const float* __restrict__ bias,
                                                float* __restrict__ dst) {
    extern __shared__ char smem[];
    const uint32_t sb = smem_u32(smem);
    const int tid = threadIdx.x, wid = tid >> 5, lane = tid & 31;
    const int n0 = blockIdx.x * 128, m0 = blockIdx.y * 128;
    const int wm = wid & 1, wn = wid >> 1;           // 2 x 4 warp grid

    // cp.async chunk mapping: per tensor 128 rows x 4 16B-chunks = 512 chunks
    const int r_ld[2]  = { (tid + 0)   >> 2, (tid + 256) >> 2 };
    const int c8_ld[2] = { (tid + 0) & 3,    (tid + 256) & 3 };

    auto issue = [&](int kt, int stage) {
        const int k0 = kt * KT;
        const uint32_t s0 = sb + stage * STAGE_B;
#pragma unroll
        for (int h = 0; h < 2; h++) {
            const int r = r_ld[h], c8 = c8_ld[h];
            const uint32_t so = (uint32_t)(r * (SSTRIDE * 2) + c8 * 16);
            const size_t ga = (size_t)(m0 + r) * DM + k0 + c8 * 8;
            const size_t gb = (size_t)(n0 + r) * DM + k0 + c8 * 8;
            CP16(s0 + 0 * TILE_B + so, Ah + ga);
            CP16(s0 + 1 * TILE_B + so, Al + ga);
            CP16(s0 + 2 * TILE_B + so, Bh + gb);
            CP16(s0 + 3 * TILE_B + so, Bl + gb);
        }
    };

    float C[4][4][4] = {};    // [m16-tile][n8-tile][frag]

    issue(0, 0);
    CPCOMMIT();
    int stage = 0;
    const int NKT = DM / KT;  // 24
    for (int kt = 0; kt < NKT; kt++) {
        if (kt + 1 < NKT) { issue(kt + 1, stage ^ 1); CPCOMMIT(); CPWAIT(1); }
        else              { CPWAIT(0); }
        __syncthreads();

        const uint32_t s0 = sb + stage * STAGE_B;
        // ldmatrix base offsets (lane-dependent)
        const uint32_t aRow = (uint32_t)(wm * 64 + (lane & 15));
        const uint32_t aK   = (uint32_t)((lane >> 4) * 8);
        const uint32_t bRow = (uint32_t)(wn * 32 + (lane & 7) + ((lane >> 4) & 1) * 8);
        const uint32_t bK   = (uint32_t)(((lane >> 3) & 1) * 8);
#pragma unroll
        for (int s = 0; s < 2; s++) {
            uint32_t ah[4][4], al[4][4], bh[2][4], bl[2][4];
#pragma unroll
            for (int mt = 0; mt < 4; mt++) {
                uint32_t off = (aRow + mt * 16) * (SSTRIDE * 2) + (aK + s * 16) * 2;
                ldmx4(ah[mt], s0 + 0 * TILE_B + off);
                ldmx4(al[mt], s0 + 1 * TILE_B + off);
            }
#pragma unroll
            for (int nt = 0; nt < 2; nt++) {
                uint32_t off = (bRow + nt * 16) * (SSTRIDE * 2) + (bK + s * 16) * 2;
                ldmx4(bh[nt], s0 + 2 * TILE_B + off);
                ldmx4(bl[nt], s0 + 3 * TILE_B + off);
            }
#pragma unroll
            for (int mt = 0; mt < 4; mt++) {
#pragma unroll
                for (int nt = 0; nt < 2; nt++) {
#pragma unroll
                    for (int ns = 0; ns < 2; ns++) {
                        float* c = C[mt][nt * 2 + ns];
                        mma16816(c, ah[mt], &bh[nt][ns * 2]);
                        mma16816(c, ah[mt], &bl[nt][ns * 2]);
                        mma16816(c, al[mt], &bh[nt][ns * 2]);
                    }
                }
            }
        }
        __syncthreads();
        stage ^= 1;
    }

    // epilogue: c0,c1 -> (row, col..col+1); c2,c3 -> (row+8, ...)
    const int g = lane >> 2, tg = lane & 3;
#pragma unroll
    for (int mt = 0; mt < 4; mt++) {
#pragma unroll
        for (int n8 = 0; n8 < 4; n8++) {
            const int col = n0 + wn * 32 + n8 * 8 + 2 * tg;
            const int row = m0 + wm * 64 + mt * 16 + g;
            const float b0 = bias[col], b1 = bias[col + 1];
            float* c = C[mt][n8];
            if (MODE == 0) {
                const int which = col / DM;
                const int hd = (col % DM) >> 6;
                const int d0 = col & 63;
                float* dp = (which == 0) ? g_Q : (which == 1) ? g_K : g_V;
                const float sc = (which == 0) ? 0.125f : 1.0f;
#pragma unroll
                for (int hrow = 0; hrow < 2; hrow++) {
                    const int m = row + hrow * 8;
                    const int bb = m >> 12, t = m & 4095;
                    float2 v;
                    v.x = (c[2 * hrow + 0] + b0) * sc;
                    v.y = (c[2 * hrow + 1] + b1) * sc;
                    *(float2*)(dp + (((size_t)(bb * NH + hd)) * TT + t) * DH + d0) = v;
                }
            } else {
#pragma unroll
                for (int hrow = 0; hrow < 2; hrow++) {
                    const int m = row + hrow * 8;
                    float2 v;
                    v.x = c[2 * hrow + 0] + b0;
                    v.y = c[2 * hrow + 1] + b1;
                    *(float2*)(dst + (size_t)m * DM + col) = v;
                }
            }
        }
    }
}

// ---------------------------------------------------------------------------
// Flash attention (round-4 best): 128q x 128k, 256 threads, 8x8 fragments.
// ---------------------------------------------------------------------------
__global__ __launch_bounds__(256) void attn_kernel(const int* __restrict__ mask,
                                                   float* __restrict__ att) {
    extern __shared__ float sm[];
    float* Qt = sm;                    // [64][128]  d-major
    float* Kt = Qt + 64 * 128;         // [64][128]  d-major
    float* Vs = Kt + 64 * 128;         // [128][64]  k-major
    float* Pt = Vs + 128 * 64;         // [128][132] q-major, padded
    float* alpha_s = Pt + 128 * 132;   // [128]

    const int tid = threadIdx.x;
    const int tx = tid & 15, ty = tid >> 4;   // S mapping
    const int dx = tid & 7,  ro = tid >> 3;   // PV mapping
    const int bh = blockIdx.y;
    const int b = bh / NH, head = bh % NH;
    const int q0 = blockIdx.x * 128;

    const float* Qp = g_Q + (size_t)bh * TT * DH;
    const float* Kp = g_K + (size_t)bh * TT * DH;
    const float* Vp = g_V + (size_t)bh * TT * DH;
    const int* mrow_g = mask + (size_t)b * TT;

    {
        int r = tid >> 2, d0 = (tid & 3) * 16;
#pragma unroll
        for (int h = 0; h < 2; h++) {
            int rr = r + 64 * h;
            const float* src = Qp + (size_t)(q0 + rr) * DH + d0;
#pragma unroll
            for (int u = 0; u < 4; u++) {
                float4 v = *(const float4*)(src + 4 * u);
                Qt[(d0 + 4 * u + 0) * 128 + rr] = v.x;
                Qt[(d0 + 4 * u + 1) * 128 + rr] = v.y;
                Qt[(d0 + 4 * u + 2) * 128 + rr] = v.z;
                Qt[(d0 + 4 * u + 3) * 128 + rr] = v.w;
            }
        }
    }

    float O[4][8] = {};
    float mr[8], lw[8];
#pragma unroll
    for (int i = 0; i < 8; i++) { mr[i] = -1e30f; lw[i] = 0.f; }

    for (int jt = 0; jt < TT / 128; jt++) {
        __syncthreads();
        {
            int r = tid >> 2, d0 = (tid & 3) * 16;
#pragma unroll
            for (int h = 0; h < 2; h++) {
                int rr = r + 64 * h;
                const float* ks = Kp + (size_t)(jt * 128 + rr) * DH + d0;
                const float* vs = Vp + (size_t)(jt * 128 + rr) * DH + d0;
#pragma unroll
                for (int u = 0; u < 4; u++) {
                    float4 kv = *(const float4*)(ks + 4 * u);
                    Kt[(d0 + 4 * u + 0) * 128 + rr] = kv.x;
                    Kt[(d0 + 4 * u + 1) * 128 + rr] = kv.y;
                    Kt[(d0 + 4 * u + 2) * 128 + rr] = kv.z;
                    Kt[(d0 + 4 * u + 3) * 128 + rr] = kv.w;
                    *(float4*)&Vs[rr * 64 + d0 + 4 * u] = *(const float4*)(vs + 4 * u);
                }
            }
        }
        int msk[8];
        {
            const int* mp = mrow_g + jt * 128 + 8 * tx;
            *(int4*)&msk[0] = *(const int4*)mp;
            *(int4*)&msk[4] = *(const int4*)(mp + 4);
        }
        __syncthreads();

        float s[8][8] = {};
#pragma unroll 8
        for (int d = 0; d < 64; d++) {
            float q[8], k[8];
            *(float4*)&q[0] = *(const float4*)&Qt[d * 128 + 8 * ty];
            *(float4*)&q[4] = *(const float4*)&Qt[d * 128 + 8 * ty + 4];
            *(float4*)&k[0] = *(const float4*)&Kt[d * 128 + 8 * tx];
            *(float4*)&k[4] = *(const float4*)&Kt[d * 128 + 8 * tx + 4];
#pragma unroll
            for (int i = 0; i < 8; i++)
#pragma unroll
                for (int j = 0; j < 8; j++)
                    s[i][j] += q[i] * k[j];
        }
#pragma unroll
        for (int j = 0; j < 8; j++) {
            if (msk[j] == 0) {
#pragma unroll
                for (int i = 0; i < 8; i++) s[i][j] = -1e9f;
            }
        }

#pragma unroll
        for (int i = 0; i < 8; i++) {
            float mx = s[i][0];
#pragma unroll
            for (int j = 1; j < 8; j++) mx = fmaxf(mx, s[i][j]);
            mx = fmaxf(mx, __shfl_xor_sync(0xffffffffu, mx, 1));
            mx = fmaxf(mx, __shfl_xor_sync(0xffffffffu, mx, 2));
            mx = fmaxf(mx, __shfl_xor_sync(0xffffffffu, mx, 4));
            mx = fmaxf(mx, __shfl_xor_sync(0xffffffffu, mx, 8));
            float mnew = fmaxf(mr[i], mx);
            float al = __expf(mr[i] - mnew);
            float sum = 0.f;
#pragma unroll
            for (int j = 0; j < 8; j++) {
                s[i][j] = __expf(s[i][j] - mnew);
                sum += s[i][j];
            }
            sum += __shfl_xor_sync(0xffffffffu, sum, 1);
            sum += __shfl_xor_sync(0xffffffffu, sum, 2);
            sum += __shfl_xor_sync(0xffffffffu, sum, 4);
            sum += __shfl_xor_sync(0xffffffffu, sum, 8);
            lw[i] = lw[i] * al + sum;
            mr[i] = mnew;
            if (tx == 0) alpha_s[8 * ty + i] = al;
            float* prow = &Pt[(8 * ty + i) * 132 + 8 * tx];
            *(float4*)prow       = make_float4(s[i][0], s[i][1], s[i][2], s[i][3]);
            *(float4*)(prow + 4) = make_float4(s[i][4], s[i][5], s[i][6], s[i][7]);
        }
        __syncthreads();

        float al4[4];
#pragma unroll
        for (int i = 0; i < 4; i++) al4[i] = alpha_s[ro + 32 * i];
#pragma unroll
        for (int i = 0; i < 4; i++)
#pragma unroll
            for (int j = 0; j < 8; j++) O[i][j] *= al4[i];

#pragma unroll 2
        for (int k4 = 0; k4 < 128; k4 += 4) {
            float p[4][4];
#pragma unroll
            for (int i = 0; i < 4; i++)
                *(float4*)p[i] = *(const float4*)&Pt[(ro + 32 * i) * 132 + k4];
#pragma unroll
            for (int u = 0; u < 4; u++) {
                float v[8];
                *(float4*)&v[0] = *(const float4*)&Vs[(k4 + u) * 64 + 8 * dx];
                *(float4*)&v[4] = *(const float4*)&Vs[(k4 + u) * 64 + 8 * dx + 4];
#pragma unroll
                for (int i = 0; i < 4; i++)
#pragma unroll
                    for (int j = 0; j < 8; j++)
                        O[i][j] += p[i][u] * v[j];
            }
        }
    }

    __syncthreads();
    if (tx == 0) {
#pragma unroll
        for (int i = 0; i < 8; i++) alpha_s[8 * ty + i] = 1.0f / lw[i];
    }
    __syncthreads();
#pragma unroll
    for (int i = 0; i < 4; i++) {
        float inv = alpha_s[ro + 32 * i];
        int t = q0 + ro + 32 * i;
        float* o = att + (((size_t)b * TT + t) * NH + head) * DH + 8 * dx;
        float4 v0, v1;
        v0.x = O[i][0] * inv; v0.y = O[i][1] * inv;
        v0.z = O[i][2] * inv; v0.w = O[i][3] * inv;
        v1.x = O[i][4] * inv; v1.y = O[i][5] * inv;
        v1.z = O[i][6] * inv; v1.w = O[i][7] * inv;
        *(float4*)o = v0;
        *(float4*)(o + 4) = v1;
    }
}

// ---------------------------------------------------------------------------
// Inputs (metadata order): x, w_qkv, b_qkv, w_out, b_out, mask. Output: float32.
// ---------------------------------------------------------------------------
extern "C" void kernel_launch(void* const* d_in, const int* in_sizes, int n_in,
                              void* d_out, int out_size) {
    const float* x     = (const float*)d_in[0];
    const float* w_qkv = (const float*)d_in[1];
    const float* b_qkv = (const float*)d_in[2];
    const float* w_out = (const float*)d_in[3];
    const float* b_out = (const float*)d_in[4];
    const int*   mask  = (const int*)d_in[5];
    float* out = (float*)d_out;

    static const size_t ATTN_SMEM =
        (2 * 64 * 128 + 128 * 64 + 128 * 132 + 128) * sizeof(float); // 166912 B
    cudaFuncSetAttribute(attn_kernel, cudaFuncAttributeMaxDynamicSharedMemorySize,
                         (int)ATTN_SMEM);
    cudaFuncSetAttribute(gemm_mma<0>, cudaFuncAttributeMaxDynamicSharedMemorySize,
                         GEMM_SMEM);
    cudaFuncSetAttribute(gemm_mma<1>, cudaFuncAttributeMaxDynamicSharedMemorySize,
                         GEMM_SMEM);

    float* att;   cudaGetSymbolAddress((void**)&att, g_att);
    __nv_bfloat16 *xh, *xl, *wqh, *wql, *woh, *wol, *ath, *atl;
    cudaGetSymbolAddress((void**)&xh,  g_xh);
    cudaGetSymbolAddress((void**)&xl,  g_xl);
    cudaGetSymbolAddress((void**)&wqh, g_wqh);
    cudaGetSymbolAddress((void**)&wql, g_wql);
    cudaGetSymbolAddress((void**)&woh, g_woh);
    cudaGetSymbolAddress((void**)&wol, g_wol);
    cudaGetSymbolAddress((void**)&ath, g_ath);
    cudaGetSymbolAddress((void**)&atl, g_atl);

    // split inputs to bf16 hi/lo
    int nx = MTOT * DM / 2, nq = 3 * DM * DM / 2, no = DM * DM / 2;
    split_kernel<<<(nx + 255) / 256, 256>>>(x, (__nv_bfloat162*)xh,
                                            (__nv_bfloat162*)xl, nx);
    split_kernel<<<(nq + 255) / 256, 256>>>(w_qkv, (__nv_bfloat162*)wqh,
                                            (__nv_bfloat162*)wql, nq);
    split_kernel<<<(no + 255) / 256, 256>>>(w_out, (__nv_bfloat162*)woh,
                                            (__nv_bfloat162*)wol, no);

    // QKV projection on tensor cores (HMMA)
    gemm_mma<0><<<dim3(3 * DM / 128, MTOT / 128), 256, GEMM_SMEM>>>(
        xh, xl, wqh, wql, b_qkv, nullptr);

    // attention (fp32 CUDA cores, round-4 version)
    attn_kernel<<<dim3(TT / 128, BH), 256, ATTN_SMEM>>>(mask, att);

    // split attention output, then out-projection on tensor cores
    split_kernel<<<(nx + 255) / 256, 256>>>(att, (__nv_bfloat162*)ath,
                                            (__nv_bfloat162*)atl, nx);
    gemm_mma<1><<<dim3(DM / 128, MTOT / 128), 256, GEMM_SMEM>>>(
        ath, atl, woh, wol, b_out, out);
}

// round 9
// speedup vs baseline: 1.6267x; 1.6267x over previous
#include <cuda_runtime.h>
#include <cuda_bf16.h>
#include <cstdint>

#define DM   768
#define NH   12
#define DH   64
#define BB   2
#define TT   4096
#define BH   (BB*NH)
#define MTOT (BB*TT)        // 8192

// ---------------- scratch (__device__ globals; no cudaMalloc allowed) ------
__device__ float g_Q[(size_t)BH*TT*DH];
__device__ float g_K[(size_t)BH*TT*DH];
__device__ float g_V[(size_t)BH*TT*DH];
__device__ float g_att[(size_t)BB*TT*DM];

__device__ __align__(256) __nv_bfloat16 g_xh[(size_t)MTOT*DM];
__device__ __align__(256) __nv_bfloat16 g_xl[(size_t)MTOT*DM];
__device__ __align__(256) __nv_bfloat16 g_wqh[(size_t)3*DM*DM];
__device__ __align__(256) __nv_bfloat16 g_wql[(size_t)3*DM*DM];
__device__ __align__(256) __nv_bfloat16 g_woh[(size_t)DM*DM];
__device__ __align__(256) __nv_bfloat16 g_wol[(size_t)DM*DM];
__device__ __align__(256) __nv_bfloat16 g_ath[(size_t)MTOT*DM];
__device__ __align__(256) __nv_bfloat16 g_atl[(size_t)MTOT*DM];

// ---------------- PTX helpers (sm_80-era: legal on plain sm_103) -----------
__device__ __forceinline__ uint32_t smem_u32(const void* p) {
    uint32_t a;
    asm("{ .reg .u64 t; cvta.to.shared.u64 t, %1; cvt.u32.u64 %0, t; }"
        : "=r"(a) : "l"(p));
    return a;
}
__device__ __forceinline__ void ldmx4(uint32_t* r, uint32_t addr) {
    asm volatile("ldmatrix.sync.aligned.m8n8.x4.shared.b16 {%0,%1,%2,%3}, [%4];"
                 : "=r"(r[0]), "=r"(r[1]), "=r"(r[2]), "=r"(r[3]) : "r"(addr));
}
__device__ __forceinline__ void mma16816(float* c, const uint32_t* a,
                                         const uint32_t* b) {
    asm volatile(
        "mma.sync.aligned.m16n8k16.row.col.f32.bf16.bf16.f32 "
        "{%0,%1,%2,%3}, {%4,%5,%6,%7}, {%8,%9}, {%0,%1,%2,%3};"
        : "+f"(c[0]), "+f"(c[1]), "+f"(c[2]), "+f"(c[3])
        : "r"(a[0]), "r"(a[1]), "r"(a[2]), "r"(a[3]), "r"(b[0]), "r"(b[1]));
}
#define CP16(saddr, gptr) \
    asm volatile("cp.async.cg.shared.global [%0], [%1], 16;" \
                 :: "r"(saddr), "l"(gptr))
#define CPCOMMIT() asm volatile("cp.async.commit_group;" ::: "memory")
#define CPWAIT(n)  asm volatile("cp.async.wait_group %0;" :: "n"(n) : "memory")

// ---------------- fp32 -> bf16 hi/lo split ----------------------------------
__global__ __launch_bounds__(256) void split_kernel(const float* __restrict__ in,
                                                    __nv_bfloat162* __restrict__ hi,
                                                    __nv_bfloat162* __restrict__ lo,
                                                    int n2) {
    int i = blockIdx.x * 256 + threadIdx.x;
    if (i < n2) {
        float2 v = ((const float2*)in)[i];
        __nv_bfloat16 hx = __float2bfloat16(v.x);
        __nv_bfloat16 hy = __float2bfloat16(v.y);
        float rx = v.x - __bfloat162float(hx);
        float ry = v.y - __bfloat162float(hy);
        hi[i] = __halves2bfloat162(hx, hy);
        lo[i] = __halves2bfloat162(__float2bfloat16(rx), __float2bfloat16(ry));
    }
}

// ---------------- HMMA GEMM: C = A @ B^T (+bias) ----------------------------
// A [M x 768] bf16 hi/lo row-major, B [N x 768] bf16 hi/lo row-major.
// CTA 128x128, 8 warps (warp tile 64x32), k-tile 32, double-buffered cp.async.
// 3-term split: C = Ah*Bh + Ah*Bl + Al*Bh.
// MODE 0: qkv scatter into g_Q/g_K/g_V (Q scaled 0.125). MODE 1: dst[m*768+n].
#define KT       32
#define SSTRIDE  40                         // bf16 per smem row (pad: 80 B)
#define TILE_B   (128 * SSTRIDE * 2)        // 10240
#define STAGE_B  (4 * TILE_B)               // 40960
#define GEMM_SMEM (2 * STAGE_B)             // 81920

template <int MODE>
__global__ __launch_bounds__(256) void gemm_mma(const __nv_bfloat16* __restrict__ Ah,
                                                const __nv_bfloat16* __restrict__ Al,
                                                const __nv_bfloat16* __restrict__ Bh,
                                                const __nv_bfloat16* __restrict__ Bl,
                                                const float* __restrict__ bias,
                                                float* __restrict__ dst) {
    extern __shared__ char smem[];
    const uint32_t sb = smem_u32(smem);
    const int tid = threadIdx.x, wid = tid >> 5, lane = tid & 31;
    const int n0 = blockIdx.x * 128, m0 = blockIdx.y * 128;
    const int wm = wid & 1, wn = wid >> 1;           // 2 x 4 warp grid

    // cp.async chunk mapping: per tensor 128 rows x 4 16B-chunks = 512 chunks
    const int r_ld[2]  = { (tid + 0)   >> 2, (tid + 256) >> 2 };
    const int c8_ld[2] = { (tid + 0) & 3,    (tid + 256) & 3 };

    auto issue = [&](int kt, int stage) {
        const int k0 = kt * KT;
        const uint32_t s0 = sb + stage * STAGE_B;
#pragma unroll
        for (int h = 0; h < 2; h++) {
            const int r = r_ld[h], c8 = c8_ld[h];
            const uint32_t so = (uint32_t)(r * (SSTRIDE * 2) + c8 * 16);
            const size_t ga = (size_t)(m0 + r) * DM + k0 + c8 * 8;
            const size_t gb = (size_t)(n0 + r) * DM + k0 + c8 * 8;
            CP16(s0 + 0 * TILE_B + so, Ah + ga);
            CP16(s0 + 1 * TILE_B + so, Al + ga);
            CP16(s0 + 2 * TILE_B + so, Bh + gb);
            CP16(s0 + 3 * TILE_B + so, Bl + gb);
        }
    };

    float C[4][4][4] = {};    // [m16-tile][n8-tile][frag]

    issue(0, 0);
    CPCOMMIT();
    int stage = 0;
    const int NKT = DM / KT;  // 24
    for (int kt = 0; kt < NKT; kt++) {
        if (kt + 1 < NKT) { issue(kt + 1, stage ^ 1); CPCOMMIT(); CPWAIT(1); }
        else              { CPWAIT(0); }
        __syncthreads();

        const uint32_t s0 = sb + stage * STAGE_B;
        // ldmatrix base offsets (lane-dependent)
        const uint32_t aRow = (uint32_t)(wm * 64 + (lane & 15));
        const uint32_t aK   = (uint32_t)((lane >> 4) * 8);
        const uint32_t bRow = (uint32_t)(wn * 32 + (lane & 7) + ((lane >> 4) & 1) * 8);
        const uint32_t bK   = (uint32_t)(((lane >> 3) & 1) * 8);
#pragma unroll
        for (int s = 0; s < 2; s++) {
            uint32_t ah[4][4], al[4][4], bh[2][4], bl[2][4];
#pragma unroll
            for (int mt = 0; mt < 4; mt++) {
                uint32_t off = (aRow + mt * 16) * (SSTRIDE * 2) + (aK + s * 16) * 2;
                ldmx4(ah[mt], s0 + 0 * TILE_B + off);
                ldmx4(al[mt], s0 + 1 * TILE_B + off);
            }
#pragma unroll
            for (int nt = 0; nt < 2; nt++) {
                uint32_t off = (bRow + nt * 16) * (SSTRIDE * 2) + (bK + s * 16) * 2;
                ldmx4(bh[nt], s0 + 2 * TILE_B + off);
                ldmx4(bl[nt], s0 + 3 * TILE_B + off);
            }
#pragma unroll
            for (int mt = 0; mt < 4; mt++) {
#pragma unroll
                for (int nt = 0; nt < 2; nt++) {
#pragma unroll
                    for (int ns = 0; ns < 2; ns++) {
                        float* c = C[mt][nt * 2 + ns];
                        mma16816(c, ah[mt], &bh[nt][ns * 2]);
                        mma16816(c, ah[mt], &bl[nt][ns * 2]);
                        mma16816(c, al[mt], &bh[nt][ns * 2]);
                    }
                }
            }
        }
        __syncthreads();
        stage ^= 1;
    }

    // epilogue: c0,c1 -> (row, col..col+1); c2,c3 -> (row+8, ...)
    const int g = lane >> 2, tg = lane & 3;
#pragma unroll
    for (int mt = 0; mt < 4; mt++) {
#pragma unroll
        for (int n8 = 0; n8 < 4; n8++) {
            const int col = n0 + wn * 32 + n8 * 8 + 2 * tg;
            const int row = m0 + wm * 64 + mt * 16 + g;
            const float b0 = bias[col], b1 = bias[col + 1];
            float* c = C[mt][n8];
            if (MODE == 0) {
                const int which = col / DM;
                const int hd = (col % DM) >> 6;
                const int d0 = col & 63;
                float* dp = (which == 0) ? g_Q : (which == 1) ? g_K : g_V;
                const float sc = (which == 0) ? 0.125f : 1.0f;
#pragma unroll
                for (int hrow = 0; hrow < 2; hrow++) {
                    const int m = row + hrow * 8;
                    const int bb = m >> 12, t = m & 4095;
                    float2 v;
                    v.x = (c[2 * hrow + 0] + b0) * sc;
                    v.y = (c[2 * hrow + 1] + b1) * sc;
                    *(float2*)(dp + (((size_t)(bb * NH + hd)) * TT + t) * DH + d0) = v;
                }
            } else {
#pragma unroll
                for (int hrow = 0; hrow < 2; hrow++) {
                    const int m = row + hrow * 8;
                    float2 v;
                    v.x = c[2 * hrow + 0] + b0;
                    v.y = c[2 * hrow + 1] + b1;
                    *(float2*)(dst + (size_t)m * DM + col) = v;
                }
            }
        }
    }
}

// ---------------------------------------------------------------------------
// Flash attention (round-4 best): 128q x 128k, 256 threads, 8x8 fragments.
// ---------------------------------------------------------------------------
__global__ __launch_bounds__(256) void attn_kernel(const int* __restrict__ mask,
                                                   float* __restrict__ att) {
    extern __shared__ float sm[];
    float* Qt = sm;                    // [64][128]  d-major
    float* Kt = Qt + 64 * 128;         // [64][128]  d-major
    float* Vs = Kt + 64 * 128;         // [128][64]  k-major
    float* Pt = Vs + 128 * 64;         // [128][132] q-major, padded
    float* alpha_s = Pt + 128 * 132;   // [128]

    const int tid = threadIdx.x;
    const int tx = tid & 15, ty = tid >> 4;   // S mapping
    const int dx = tid & 7,  ro = tid >> 3;   // PV mapping
    const int bh = blockIdx.y;
    const int b = bh / NH, head = bh % NH;
    const int q0 = blockIdx.x * 128;

    const float* Qp = g_Q + (size_t)bh * TT * DH;
    const float* Kp = g_K + (size_t)bh * TT * DH;
    const float* Vp = g_V + (size_t)bh * TT * DH;
    const int* mrow_g = mask + (size_t)b * TT;

    {
        int r = tid >> 2, d0 = (tid & 3) * 16;
#pragma unroll
        for (int h = 0; h < 2; h++) {
            int rr = r + 64 * h;
            const float* src = Qp + (size_t)(q0 + rr) * DH + d0;
#pragma unroll
            for (int u = 0; u < 4; u++) {
                float4 v = *(const float4*)(src + 4 * u);
                Qt[(d0 + 4 * u + 0) * 128 + rr] = v.x;
                Qt[(d0 + 4 * u + 1) * 128 + rr] = v.y;
                Qt[(d0 + 4 * u + 2) * 128 + rr] = v.z;
                Qt[(d0 + 4 * u + 3) * 128 + rr] = v.w;
            }
        }
    }

    float O[4][8] = {};
    float mr[8], lw[8];
#pragma unroll
    for (int i = 0; i < 8; i++) { mr[i] = -1e30f; lw[i] = 0.f; }

    for (int jt = 0; jt < TT / 128; jt++) {
        __syncthreads();
        {
            int r = tid >> 2, d0 = (tid & 3) * 16;
#pragma unroll
            for (int h = 0; h < 2; h++) {
                int rr = r + 64 * h;
                const float* ks = Kp + (size_t)(jt * 128 + rr) * DH + d0;
                const float* vs = Vp + (size_t)(jt * 128 + rr) * DH + d0;
#pragma unroll
                for (int u = 0; u < 4; u++) {
                    float4 kv = *(const float4*)(ks + 4 * u);
                    Kt[(d0 + 4 * u + 0) * 128 + rr] = kv.x;
                    Kt[(d0 + 4 * u + 1) * 128 + rr] = kv.y;
                    Kt[(d0 + 4 * u + 2) * 128 + rr] = kv.z;
                    Kt[(d0 + 4 * u + 3) * 128 + rr] = kv.w;
                    *(float4*)&Vs[rr * 64 + d0 + 4 * u] = *(const float4*)(vs + 4 * u);
                }
            }
        }
        int msk[8];
        {
            const int* mp = mrow_g + jt * 128 + 8 * tx;
            *(int4*)&msk[0] = *(const int4*)mp;
            *(int4*)&msk[4] = *(const int4*)(mp + 4);
        }
        __syncthreads();

        float s[8][8] = {};
#pragma unroll 8
        for (int d = 0; d < 64; d++) {
            float q[8], k[8];
            *(float4*)&q[0] = *(const float4*)&Qt[d * 128 + 8 * ty];
            *(float4*)&q[4] = *(const float4*)&Qt[d * 128 + 8 * ty + 4];
            *(float4*)&k[0] = *(const float4*)&Kt[d * 128 + 8 * tx];
            *(float4*)&k[4] = *(const float4*)&Kt[d * 128 + 8 * tx + 4];
#pragma unroll
            for (int i = 0; i < 8; i++)
#pragma unroll
                for (int j = 0; j < 8; j++)
                    s[i][j] += q[i] * k[j];
        }
#pragma unroll
        for (int j = 0; j < 8; j++) {
            if (msk[j] == 0) {
#pragma unroll
                for (int i = 0; i < 8; i++) s[i][j] = -1e9f;
            }
        }

#pragma unroll
        for (int i = 0; i < 8; i++) {
            float mx = s[i][0];
#pragma unroll
            for (int j = 1; j < 8; j++) mx = fmaxf(mx, s[i][j]);
            mx = fmaxf(mx, __shfl_xor_sync(0xffffffffu, mx, 1));
            mx = fmaxf(mx, __shfl_xor_sync(0xffffffffu, mx, 2));
            mx = fmaxf(mx, __shfl_xor_sync(0xffffffffu, mx, 4));
            mx = fmaxf(mx, __shfl_xor_sync(0xffffffffu, mx, 8));
            float mnew = fmaxf(mr[i], mx);
            float al = __expf(mr[i] - mnew);
            float sum = 0.f;
#pragma unroll
            for (int j = 0; j < 8; j++) {
                s[i][j] = __expf(s[i][j] - mnew);
                sum += s[i][j];
            }
            sum += __shfl_xor_sync(0xffffffffu, sum, 1);
            sum += __shfl_xor_sync(0xffffffffu, sum, 2);
            sum += __shfl_xor_sync(0xffffffffu, sum, 4);
            sum += __shfl_xor_sync(0xffffffffu, sum, 8);
            lw[i] = lw[i] * al + sum;
            mr[i] = mnew;
            if (tx == 0) alpha_s[8 * ty + i] = al;
            float* prow = &Pt[(8 * ty + i) * 132 + 8 * tx];
            *(float4*)prow       = make_float4(s[i][0], s[i][1], s[i][2], s[i][3]);
            *(float4*)(prow + 4) = make_float4(s[i][4], s[i][5], s[i][6], s[i][7]);
        }
        __syncthreads();

        float al4[4];
#pragma unroll
        for (int i = 0; i < 4; i++) al4[i] = alpha_s[ro + 32 * i];
#pragma unroll
        for (int i = 0; i < 4; i++)
#pragma unroll
            for (int j = 0; j < 8; j++) O[i][j] *= al4[i];

#pragma unroll 2
        for (int k4 = 0; k4 < 128; k4 += 4) {
            float p[4][4];
#pragma unroll
            for (int i = 0; i < 4; i++)
                *(float4*)p[i] = *(const float4*)&Pt[(ro + 32 * i) * 132 + k4];
#pragma unroll
            for (int u = 0; u < 4; u++) {
                float v[8];
                *(float4*)&v[0] = *(const float4*)&Vs[(k4 + u) * 64 + 8 * dx];
                *(float4*)&v[4] = *(const float4*)&Vs[(k4 + u) * 64 + 8 * dx + 4];
#pragma unroll
                for (int i = 0; i < 4; i++)
#pragma unroll
                    for (int j = 0; j < 8; j++)
                        O[i][j] += p[i][u] * v[j];
            }
        }
    }

    __syncthreads();
    if (tx == 0) {
#pragma unroll
        for (int i = 0; i < 8; i++) alpha_s[8 * ty + i] = 1.0f / lw[i];
    }
    __syncthreads();
#pragma unroll
    for (int i = 0; i < 4; i++) {
        float inv = alpha_s[ro + 32 * i];
        int t = q0 + ro + 32 * i;
        float* o = att + (((size_t)b * TT + t) * NH + head) * DH + 8 * dx;
        float4 v0, v1;
        v0.x = O[i][0] * inv; v0.y = O[i][1] * inv;
        v0.z = O[i][2] * inv; v0.w = O[i][3] * inv;
        v1.x = O[i][4] * inv; v1.y = O[i][5] * inv;
        v1.z = O[i][6] * inv; v1.w = O[i][7] * inv;
        *(float4*)o = v0;
        *(float4*)(o + 4) = v1;
    }
}

// ---------------------------------------------------------------------------
// Inputs (metadata order): x, w_qkv, b_qkv, w_out, b_out, mask. Output: float32.
// ---------------------------------------------------------------------------
extern "C" void kernel_launch(void* const* d_in, const int* in_sizes, int n_in,
                              void* d_out, int out_size) {
    const float* x     = (const float*)d_in[0];
    const float* w_qkv = (const float*)d_in[1];
    const float* b_qkv = (const float*)d_in[2];
    const float* w_out = (const float*)d_in[3];
    const float* b_out = (const float*)d_in[4];
    const int*   mask  = (const int*)d_in[5];
    float* out = (float*)d_out;

    static const size_t ATTN_SMEM =
        (2 * 64 * 128 + 128 * 64 + 128 * 132 + 128) * sizeof(float); // 166912 B
    cudaFuncSetAttribute(attn_kernel, cudaFuncAttributeMaxDynamicSharedMemorySize,
                         (int)ATTN_SMEM);
    cudaFuncSetAttribute(gemm_mma<0>, cudaFuncAttributeMaxDynamicSharedMemorySize,
                         GEMM_SMEM);
    cudaFuncSetAttribute(gemm_mma<1>, cudaFuncAttributeMaxDynamicSharedMemorySize,
                         GEMM_SMEM);

    float* att;   cudaGetSymbolAddress((void**)&att, g_att);
    __nv_bfloat16 *xh, *xl, *wqh, *wql, *woh, *wol, *ath, *atl;
    cudaGetSymbolAddress((void**)&xh,  g_xh);
    cudaGetSymbolAddress((void**)&xl,  g_xl);
    cudaGetSymbolAddress((void**)&wqh, g_wqh);
    cudaGetSymbolAddress((void**)&wql, g_wql);
    cudaGetSymbolAddress((void**)&woh, g_woh);
    cudaGetSymbolAddress((void**)&wol, g_wol);
    cudaGetSymbolAddress((void**)&ath, g_ath);
    cudaGetSymbolAddress((void**)&atl, g_atl);

    // split inputs to bf16 hi/lo
    int nx = MTOT * DM / 2, nq = 3 * DM * DM / 2, no = DM * DM / 2;
    split_kernel<<<(nx + 255) / 256, 256>>>(x, (__nv_bfloat162*)xh,
                                            (__nv_bfloat162*)xl, nx);
    split_kernel<<<(nq + 255) / 256, 256>>>(w_qkv, (__nv_bfloat162*)wqh,
                                            (__nv_bfloat162*)wql, nq);
    split_kernel<<<(no + 255) / 256, 256>>>(w_out, (__nv_bfloat162*)woh,
                                            (__nv_bfloat162*)wol, no);

    // QKV projection on tensor cores (HMMA)
    gemm_mma<0><<<dim3(3 * DM / 128, MTOT / 128), 256, GEMM_SMEM>>>(
        xh, xl, wqh, wql, b_qkv, nullptr);

    // attention (fp32 CUDA cores, round-4 version)
    attn_kernel<<<dim3(TT / 128, BH), 256, ATTN_SMEM>>>(mask, att);

    // split attention output, then out-projection on tensor cores
    split_kernel<<<(nx + 255) / 256, 256>>>(att, (__nv_bfloat162*)ath,
                                            (__nv_bfloat162*)atl, nx);
    gemm_mma<1><<<dim3(DM / 128, MTOT / 128), 256, GEMM_SMEM>>>(
        ath, atl, woh, wol, b_out, out);
}